// round 4
// baseline (speedup 1.0000x reference)
#include <cuda_runtime.h>
#include <cstdint>

#define BB       8
#define NN       8192
#define NPOINT   1024
#define NSAMPLE  32
#define CFEAT    64
#define CIN0     67      // 3 + 64

// ------------------------------------------------------------------
// scratch (no allocations allowed) : ball-query group indices
// ------------------------------------------------------------------
__device__ int g_gidx[BB * NPOINT * NSAMPLE];

// ------------------------------------------------------------------
// packed f32x2 helpers (Blackwell sm_103a)
// ------------------------------------------------------------------
__device__ __forceinline__ unsigned long long pk2(float lo, float hi) {
    unsigned long long r;
    asm("mov.b64 %0, {%1, %2};" : "=l"(r) : "f"(lo), "f"(hi));
    return r;
}
__device__ __forceinline__ void upk2(unsigned long long v, float& lo, float& hi) {
    asm("mov.b64 {%0, %1}, %2;" : "=f"(lo), "=f"(hi) : "l"(v));
}
__device__ __forceinline__ unsigned long long add2_(unsigned long long a, unsigned long long b) {
    unsigned long long r;
    asm("add.rn.f32x2 %0, %1, %2;" : "=l"(r) : "l"(a), "l"(b));
    return r;
}
__device__ __forceinline__ unsigned long long mul2_(unsigned long long a, unsigned long long b) {
    unsigned long long r;
    asm("mul.rn.f32x2 %0, %1, %2;" : "=l"(r) : "l"(a), "l"(b));
    return r;
}
__device__ __forceinline__ unsigned long long fma2_(unsigned long long a, unsigned long long b,
                                                    unsigned long long c) {
    unsigned long long r;
    asm("fma.rn.f32x2 %0, %1, %2, %3;" : "=l"(r) : "l"(a), "l"(b), "l"(c));
    return r;
}

// ==================================================================
// Kernel 1: furthest point sampling. One block per batch.
// 1024 threads x 8 points in registers (packed f32x2 pairs) —
// 8 warps/SMSP to hide REDUX/LDS/barrier latency (fma-pipe work per
// SMSP is constant; extra warps raise issue efficiency).
// Single barrier per iteration; partial arrays double-buffered by
// iteration parity. Bit-exact vs reference (rn ops, no fma
// contraction, first-max-index tiebreak).
// ==================================================================
#define FPS_T 1024
#define FPS_P (NN / FPS_T)   // 8

__global__ void __launch_bounds__(FPS_T, 1)
fps_kernel(const float* __restrict__ xyz, float* __restrict__ newxyz)
{
    extern __shared__ float sm[];
    float* sx = sm;
    float* sy = sm + NN;
    float* sz = sm + 2 * NN;
    unsigned* wv = (unsigned*)(sm + 3 * NN);   // [2][32] warp value partials
    unsigned* wi = wv + 64;                    // [2][32] warp index partials

    const int b = blockIdx.x;
    const float* bx = xyz + (size_t)b * NN * 3;
    float* out = newxyz + (size_t)b * NPOINT * 3;
    const int t = threadIdx.x;
    const int lane = t & 31;
    const int warp = t >> 5;

    unsigned long long px2[FPS_P / 2], py2[FPS_P / 2], pz2[FPS_P / 2];
    float mind[FPS_P];
#pragma unroll
    for (int k = 0; k < FPS_P / 2; k++) {
        int i0 = t * FPS_P + 2 * k;
        int i1 = i0 + 1;
        float x0 = bx[i0 * 3 + 0], y0 = bx[i0 * 3 + 1], z0 = bx[i0 * 3 + 2];
        float x1 = bx[i1 * 3 + 0], y1 = bx[i1 * 3 + 1], z1 = bx[i1 * 3 + 2];
        px2[k] = pk2(x0, x1); py2[k] = pk2(y0, y1); pz2[k] = pk2(z0, z1);
        sx[i0] = x0; sy[i0] = y0; sz[i0] = z0;
        sx[i1] = x1; sy[i1] = y1; sz[i1] = z1;
        mind[2 * k] = 1e10f; mind[2 * k + 1] = 1e10f;
    }
    __syncthreads();

    float qx = sx[0], qy = sy[0], qz = sz[0];
    if (t == 0) { out[0] = qx; out[1] = qy; out[2] = qz; }

    for (int it = 1; it < NPOINT; it++) {
        const unsigned long long nqx = pk2(-qx, -qx);
        const unsigned long long nqy = pk2(-qy, -qy);
        const unsigned long long nqz = pk2(-qz, -qz);
        float vloc = -1.0f;
#pragma unroll
        for (int k = 0; k < FPS_P / 2; k++) {
            unsigned long long dx = add2_(px2[k], nqx);
            unsigned long long dy = add2_(py2[k], nqy);
            unsigned long long dz = add2_(pz2[k], nqz);
            unsigned long long d2 = add2_(add2_(mul2_(dx, dx), mul2_(dy, dy)),
                                          mul2_(dz, dz));
            float d0, d1;
            upk2(d2, d0, d1);
            float m0 = fminf(mind[2 * k], d0);
            float m1 = fminf(mind[2 * k + 1], d1);
            mind[2 * k] = m0;
            mind[2 * k + 1] = m1;
            vloc = fmaxf(vloc, fmaxf(m0, m1));
        }
        // ---- pre-barrier, per-warp phase ----
        unsigned wmax = __reduce_max_sync(0xffffffffu, __float_as_uint(vloc));
        float wmaxf = __uint_as_float(wmax);
        unsigned idxl = 0xffffffffu;
#pragma unroll
        for (int j = FPS_P - 1; j >= 0; j--)
            if (mind[j] == wmaxf) idxl = t * FPS_P + j;
        unsigned widx = __reduce_min_sync(0xffffffffu, idxl);

        const int par = (it & 1) << 5;      // double-buffer slot
        if (lane == 0) { wv[par + warp] = wmax; wi[par + warp] = widx; }
        __syncthreads();

        // ---- post-barrier combine (redundant across all warps) ----
        unsigned bvv = wv[par + lane];
        unsigned bii = wi[par + lane];
        unsigned vmax = __reduce_max_sync(0xffffffffu, bvv);
        unsigned bi   = __reduce_min_sync(0xffffffffu,
                                          (bvv == vmax) ? bii : 0xffffffffu);

        qx = sx[bi]; qy = sy[bi]; qz = sz[bi];
        if (t == 0) {
            out[it * 3 + 0] = qx;
            out[it * 3 + 1] = qy;
            out[it * 3 + 2] = qz;
        }
    }
}

// ==================================================================
// Kernel 2: ball query. One warp per center; index-order scan in
// chunks of 32 with ballot/popc slot assignment, early exit.
// ==================================================================
__global__ void __launch_bounds__(256)
ballquery_kernel(const float* __restrict__ xyz, const float* __restrict__ newxyz)
{
    const int gw   = (blockIdx.x * blockDim.x + threadIdx.x) >> 5;
    const int lane = threadIdx.x & 31;
    if (gw >= BB * NPOINT) return;
    const int b = gw >> 10;
    const float* bx = xyz + (size_t)b * NN * 3;
    const float cx = newxyz[gw * 3 + 0];
    const float cy = newxyz[gw * 3 + 1];
    const float cz = newxyz[gw * 3 + 2];
    int* out = g_gidx + gw * NSAMPLE;
    const float R2 = (float)0.04;

    int cnt = 0, firstIdx = 0;
    for (int base = 0; base < NN; base += 32) {
        const int i = base + lane;
        float dx = __fsub_rn(bx[i * 3 + 0], cx);
        float dy = __fsub_rn(bx[i * 3 + 1], cy);
        float dz = __fsub_rn(bx[i * 3 + 2], cz);
        float d  = __fadd_rn(__fadd_rn(__fmul_rn(dx, dx), __fmul_rn(dy, dy)),
                             __fmul_rn(dz, dz));
        bool in = d < R2;
        unsigned mask = __ballot_sync(0xffffffffu, in);
        if (mask) {
            if (cnt == 0) firstIdx = base + (__ffs(mask) - 1);
            if (in) {
                int slot = cnt + __popc(mask & ((1u << lane) - 1u));
                if (slot < NSAMPLE) out[slot] = i;
            }
            cnt += __popc(mask);
            if (cnt >= NSAMPLE) break;
        }
    }
    if (lane >= cnt) out[lane] = (cnt > 0) ? firstIdx : 0;
}

// ==================================================================
// Kernel 3: gather + 3-layer MLP + maxpool, thread-per-sample.
// Warp = one group (32 lanes = 32 samples). Each thread computes all
// channels of its own sample; activations in a private smem row
// (pitch 71, conflict-free), weights broadcast from smem.
// NO barriers after weight load. Maxpool = in-warp shuffle butterfly.
// Packed f32x2 FMA with per-channel accumulation order identical to
// the scalar reference.
// ==================================================================
#define MLP_T   512
#define GPB     16              // groups per block (= warps)
#define RPITCH  71              // activation row pitch (stride 7 mod 32)

__global__ void __launch_bounds__(MLP_T)
mlp_kernel(const float* __restrict__ xyz, const float* __restrict__ feat,
           const float* __restrict__ w0, const float* __restrict__ s0g, const float* __restrict__ b0g,
           const float* __restrict__ w1, const float* __restrict__ s1g, const float* __restrict__ b1g,
           const float* __restrict__ w2, const float* __restrict__ s2g, const float* __restrict__ b2g,
           const float* __restrict__ newxyz, float* __restrict__ outfeat)
{
    extern __shared__ float sm[];
    float* w0s = sm;                    // 67*64
    float* w1s = w0s + CIN0 * 64;       // 64*64
    float* w2s = w1s + 64 * 64;         // 64*128
    float* sc0 = w2s + 64 * 128;
    float* bi0 = sc0 + 64;
    float* sc1 = bi0 + 64;
    float* bi1 = sc1 + 64;
    float* sc2 = bi1 + 64;              // 128
    float* bi2 = sc2 + 128;             // 128
    float* xr  = bi2 + 128;             // 512 * 71

    const int t = threadIdx.x;
    const int lane = t & 31;            // sample within group
    const int g = t >> 5;               // group within block

    for (int i = t; i < CIN0 * 64; i += MLP_T) { int o = i & 63,  c = i >> 6; w0s[i] = w0[o * CIN0 + c]; }
    for (int i = t; i < 64 * 64;  i += MLP_T) { int o = i & 63,  c = i >> 6; w1s[i] = w1[o * 64 + c]; }
    for (int i = t; i < 64 * 128; i += MLP_T) { int o = i & 127, c = i >> 7; w2s[i] = w2[o * 64 + c]; }
    if (t < 64)  { sc0[t] = s0g[t]; bi0[t] = b0g[t]; sc1[t] = s1g[t]; bi1[t] = b1g[t]; }
    if (t < 128) { sc2[t] = s2g[t]; bi2[t] = b2g[t]; }
    __syncthreads();

    const int gi = blockIdx.x * GPB + g;
    const int b  = gi >> 10;
    const int s  = gi & 1023;
    const int pi = g_gidx[gi * NSAMPLE + lane];

    float* row = xr + t * RPITCH;       // [0:3] dxyz, [4:68] feat

    // ---- gather (all private; no sync) ----
    {
        const float cx = newxyz[gi * 3 + 0];
        const float cy = newxyz[gi * 3 + 1];
        const float cz = newxyz[gi * 3 + 2];
        const float* prow = xyz + ((size_t)b * NN + pi) * 3;
        row[0] = __fsub_rn(prow[0], cx);
        row[1] = __fsub_rn(prow[1], cy);
        row[2] = __fsub_rn(prow[2], cz);
        const float4* frow = (const float4*)(feat + ((size_t)b * NN + pi) * CFEAT);
#pragma unroll
        for (int k = 0; k < 16; k++) {
            float4 f = frow[k];
            row[4 + 4 * k + 0] = f.x;
            row[4 + 4 * k + 1] = f.y;
            row[4 + 4 * k + 2] = f.z;
            row[4 + 4 * k + 3] = f.w;
        }
    }

    // ---- layer 0: 67 -> 64 (all 64 ch in 32 packed accumulators) ----
    {
        unsigned long long acc[32];
#pragma unroll
        for (int q = 0; q < 32; q++) acc[q] = 0ull;
#pragma unroll 2
        for (int c = 0; c < CIN0; c++) {
            float xv = row[c + (c >= 3)];   // skip pad slot at [3]
            unsigned long long xv2 = pk2(xv, xv);
            const ulonglong2* wr = (const ulonglong2*)(w0s + c * 64);
#pragma unroll
            for (int q = 0; q < 16; q++) {
                ulonglong2 w = wr[q];
                acc[2 * q]     = fma2_(xv2, w.x, acc[2 * q]);
                acc[2 * q + 1] = fma2_(xv2, w.y, acc[2 * q + 1]);
            }
        }
#pragma unroll
        for (int q = 0; q < 32; q++) {
            float a0, a1;
            upk2(acc[q], a0, a1);
            float v0 = __fadd_rn(__fmul_rn(a0, sc0[2 * q]),     bi0[2 * q]);
            float v1 = __fadd_rn(__fmul_rn(a1, sc0[2 * q + 1]), bi0[2 * q + 1]);
            row[2 * q]     = fmaxf(v0, 0.0f);
            row[2 * q + 1] = fmaxf(v1, 0.0f);
        }
    }

    // ---- layer 1: 64 -> 64 ----
    {
        unsigned long long acc[32];
#pragma unroll
        for (int q = 0; q < 32; q++) acc[q] = 0ull;
#pragma unroll 2
        for (int c = 0; c < 64; c++) {
            float xv = row[c];
            unsigned long long xv2 = pk2(xv, xv);
            const ulonglong2* wr = (const ulonglong2*)(w1s + c * 64);
#pragma unroll
            for (int q = 0; q < 16; q++) {
                ulonglong2 w = wr[q];
                acc[2 * q]     = fma2_(xv2, w.x, acc[2 * q]);
                acc[2 * q + 1] = fma2_(xv2, w.y, acc[2 * q + 1]);
            }
        }
        // h2 must not overwrite row while still reading: loop reads all c
        // before epilogue writes -> safe in-place.
#pragma unroll
        for (int q = 0; q < 32; q++) {
            float a0, a1;
            upk2(acc[q], a0, a1);
            float v0 = __fadd_rn(__fmul_rn(a0, sc1[2 * q]),     bi1[2 * q]);
            float v1 = __fadd_rn(__fmul_rn(a1, sc1[2 * q + 1]), bi1[2 * q + 1]);
            row[2 * q]     = fmaxf(v0, 0.0f);
            row[2 * q + 1] = fmaxf(v1, 0.0f);
        }
    }

    // ---- layer 2: 64 -> 128 in 4 quarters of 32 ch; maxpool by
    //      in-warp butterfly (lanes = the 32 samples of this group) ----
    const size_t outbase = (size_t)b * 128 * NPOINT + s;
#pragma unroll 1
    for (int qt = 0; qt < 4; qt++) {
        unsigned long long acc[16];
#pragma unroll
        for (int q = 0; q < 16; q++) acc[q] = 0ull;
#pragma unroll 2
        for (int c = 0; c < 64; c++) {
            float xv = row[c];
            unsigned long long xv2 = pk2(xv, xv);
            const ulonglong2* wr = (const ulonglong2*)(w2s + c * 128 + qt * 32);
#pragma unroll
            for (int q = 0; q < 8; q++) {
                ulonglong2 w = wr[q];
                acc[2 * q]     = fma2_(xv2, w.x, acc[2 * q]);
                acc[2 * q + 1] = fma2_(xv2, w.y, acc[2 * q + 1]);
            }
        }
        float v[32];
#pragma unroll
        for (int q = 0; q < 16; q++) {
            float a0, a1;
            upk2(acc[q], a0, a1);
            int o = qt * 32 + 2 * q;
            float v0 = __fadd_rn(__fmul_rn(a0, sc2[o]),     bi2[o]);
            float v1 = __fadd_rn(__fmul_rn(a1, sc2[o + 1]), bi2[o + 1]);
            v[2 * q]     = fmaxf(v0, 0.0f);
            v[2 * q + 1] = fmaxf(v1, 0.0f);
        }
        // maxpool across the 32 lanes (samples) via butterfly
#pragma unroll
        for (int st = 16; st > 0; st >>= 1) {
#pragma unroll
            for (int i = 0; i < 32; i++)
                v[i] = fmaxf(v[i], __shfl_xor_sync(0xffffffffu, v[i], st));
        }
        // lane i writes channel qt*32 + i  (all lanes hold all maxes)
#pragma unroll
        for (int i = 0; i < 32; i++)
            if (lane == i)
                outfeat[outbase + (size_t)(qt * 32 + i) * NPOINT] = v[i];
    }
}

// ==================================================================
// launch
// ==================================================================
extern "C" void kernel_launch(void* const* d_in, const int* in_sizes, int n_in,
                              void* d_out, int out_size)
{
    (void)in_sizes; (void)n_in; (void)out_size;
    const float* xyz  = (const float*)d_in[0];
    const float* feat = (const float*)d_in[1];
    const float* w0 = (const float*)d_in[2];
    const float* s0 = (const float*)d_in[3];
    const float* b0 = (const float*)d_in[4];
    const float* w1 = (const float*)d_in[5];
    const float* s1 = (const float*)d_in[6];
    const float* b1 = (const float*)d_in[7];
    const float* w2 = (const float*)d_in[8];
    const float* s2 = (const float*)d_in[9];
    const float* b2 = (const float*)d_in[10];

    float* out     = (float*)d_out;
    float* newxyz  = out;                            // (B, NPOINT, 3)
    float* outfeat = out + (size_t)BB * NPOINT * 3;  // (B, 128, NPOINT)

    const int FPS_SMEM = (3 * NN + 128) * 4 + 16;
    const int MLP_SMEM = (CIN0 * 64 + 64 * 64 + 64 * 128 + 512 + MLP_T * RPITCH) * 4;
    cudaFuncSetAttribute(fps_kernel, cudaFuncAttributeMaxDynamicSharedMemorySize, FPS_SMEM);
    cudaFuncSetAttribute(mlp_kernel, cudaFuncAttributeMaxDynamicSharedMemorySize, MLP_SMEM);

    fps_kernel<<<BB, FPS_T, FPS_SMEM>>>(xyz, newxyz);
    ballquery_kernel<<<(BB * NPOINT * 32) / 256, 256>>>(xyz, newxyz);
    mlp_kernel<<<BB * NPOINT / GPB, MLP_T, MLP_SMEM>>>(
        xyz, feat, w0, s0, b0, w1, s1, b1, w2, s2, b2, newxyz, outfeat);
}